// round 11
// baseline (speedup 1.0000x reference)
#include <cuda_runtime.h>
#include <cuda_bf16.h>

// Problem constants (fixed by the reference setup)
#define B_    64
#define NA_   2048
#define NTOT_ (B_ * NA_)        // 131072 atoms
#define EG_   40960             // directed edges per graph
#define E_    (B_ * EG_)        // 2,621,440 input edges
#define E2_   (2 * E_)          // 5,242,880 symmetrized edges

#define THREADS_  512
#define EPT_      4                     // edges per thread
#define EPB_      (THREADS_ * EPT_)     // 2048 edges/block; EG_ % EPB_ == 0 (20 blocks/graph)
#define GRID_     (E_ / EPB_)           // 1280

// Output layout: tuple members flattened row-major and concatenated, cast to f32
#define BASE_EI   0
#define BASE_OFF  (2 * E2_)                 // 10,485,760
#define BASE_DIST (BASE_OFF + 3 * E2_)      // 26,214,400
#define BASE_VEC  (BASE_DIST + E2_)         // 31,457,280
#define BASE_NN   (BASE_VEC + 3 * E2_)      // 47,185,920
#define BASE_SWAP (BASE_NN + B_)            // 47,185,984

__global__ __launch_bounds__(THREADS_, 2)   // cap regs at 64; >=50% occupancy
void graph_edges_kernel(const float* __restrict__ pos,
                        const float* __restrict__ cell,
                        const void*  __restrict__ ei_raw,
                        const int*   __restrict__ off,
                        const void*  __restrict__ nn_raw,
                        float*       __restrict__ out)
{
    __shared__ float4 s_pos[NA_];          // 32 KB: this graph's padded positions
    __shared__ int    s_is64;

    const int tid = threadIdx.x;
    const int blk = blockIdx.x;
    const int b     = blk / (EG_ / EPB_);  // graph id
    const int chunk = blk % (EG_ / EPB_);
    const int e0    = b * EG_ + chunk * EPB_;

    // Per-block dtype detection: true int64 atom indices are < 2^31; int32
    // data reinterpreted as u64 packs a (nonzero w.o.p.) src index in the
    // high half within the first 8 words.
    if (tid == 0) {
        const unsigned long long* eu = (const unsigned long long*)ei_raw;
        int is64 = 1;
        #pragma unroll
        for (int k = 0; k < 8; ++k)
            if (eu[k] >= (1ULL << 31)) { is64 = 0; break; }
        s_is64 = is64;
    }

    // Cooperative coalesced load of this graph's positions, padded to float4.
    {
        const float* pb = pos + (size_t)b * NA_ * 3;
        float* sp = (float*)s_pos;
        #pragma unroll
        for (int i = tid; i < NA_ * 3; i += THREADS_) {
            const int atom = i / 3;
            const int comp = i - atom * 3;
            sp[atom * 4 + comp] = pb[i];
        }
    }
    __syncthreads();
    const int is64 = s_is64;

    // cell[b] broadcast (L1-resident)
    const float* cb = cell + 9 * b;
    const float c00 = cb[0], c01 = cb[1], c02 = cb[2];
    const float c10 = cb[3], c11 = cb[4], c12 = cb[5];
    const float c20 = cb[6], c21 = cb[7], c22 = cb[8];

    const int abase = b * NA_;
    const int e = e0 + 4 * tid;            // this thread handles edges e..e+3 (e % 4 == 0)

    // ---- indices (vector loads) ----
    int iv[4], jv[4];
    if (is64) {
        const long long* ei = (const long long*)ei_raw;
        const longlong2 iA = __ldcs((const longlong2*)(ei + e));
        const longlong2 iB = __ldcs((const longlong2*)(ei + e + 2));
        const longlong2 jA = __ldcs((const longlong2*)(ei + E_ + e));
        const longlong2 jB = __ldcs((const longlong2*)(ei + E_ + e + 2));
        iv[0] = (int)iA.x; iv[1] = (int)iA.y; iv[2] = (int)iB.x; iv[3] = (int)iB.y;
        jv[0] = (int)jA.x; jv[1] = (int)jA.y; jv[2] = (int)jB.x; jv[3] = (int)jB.y;
    } else {
        const int* ei = (const int*)ei_raw;
        const int4 iA = __ldcs((const int4*)(ei + e));
        const int4 jA = __ldcs((const int4*)(ei + E_ + e));
        iv[0] = iA.x; iv[1] = iA.y; iv[2] = iA.z; iv[3] = iA.w;
        jv[0] = jA.x; jv[1] = jA.y; jv[2] = jA.z; jv[3] = jA.w;
    }

    // ---- cell offsets: 12 ints as 3 x int4 ----
    const int4 q0 = __ldcs((const int4*)(off + 3 * e));
    const int4 q1 = __ldcs((const int4*)(off + 3 * e + 4));
    const int4 q2 = __ldcs((const int4*)(off + 3 * e + 8));
    float of[12];
    of[0] = (float)q0.x; of[1]  = (float)q0.y; of[2]  = (float)q0.z; of[3]  = (float)q0.w;
    of[4] = (float)q1.x; of[5]  = (float)q1.y; of[6]  = (float)q1.z; of[7]  = (float)q1.w;
    of[8] = (float)q2.x; of[9]  = (float)q2.y; of[10] = (float)q2.z; of[11] = (float)q2.w;

    // ---- per-edge compute ----
    float d[4], vx[4], vy[4], vz[4];
    #pragma unroll
    for (int k = 0; k < 4; ++k) {
        const float g0 = of[3 * k], g1 = of[3 * k + 1], g2 = of[3 * k + 2];
        const float4 pi = s_pos[iv[k] - abase];
        const float4 pj = s_pos[jv[k] - abase];
        const float dx = pi.x - pj.x + (g0 * c00 + g1 * c10 + g2 * c20);
        const float dy = pi.y - pj.y + (g0 * c01 + g1 * c11 + g2 * c21);
        const float dz = pi.z - pj.z + (g0 * c02 + g1 * c12 + g2 * c22);
        d[k] = sqrtf(dx * dx + dy * dy + dz * dz);
        const float n = -1.0f / d[k];
        vx[k] = dx * n; vy[k] = dy * n; vz[k] = dz * n;
    }

    // symmetrized slots: fwd f = e + b*EG (mult of 4), bwd w = f + EG (mult of 4)
    const int f = e + b * EG_;
    const int w = f + EG_;

    const float4 fiv = make_float4((float)iv[0], (float)iv[1], (float)iv[2], (float)iv[3]);
    const float4 fjv = make_float4((float)jv[0], (float)jv[1], (float)jv[2], (float)jv[3]);

    // ei_sym [2, E2]
    __stcs((float4*)&out[BASE_EI + f],       fiv);
    __stcs((float4*)&out[BASE_EI + E2_ + f], fjv);
    __stcs((float4*)&out[BASE_EI + w],       fjv);
    __stcs((float4*)&out[BASE_EI + E2_ + w], fiv);

    // off_sym [E2, 3] (12 contiguous floats per 4-edge group)
    float* po = out + BASE_OFF;
    __stcs((float4*)&po[3 * f],     make_float4(of[0], of[1], of[2], of[3]));
    __stcs((float4*)&po[3 * f + 4], make_float4(of[4], of[5], of[6], of[7]));
    __stcs((float4*)&po[3 * f + 8], make_float4(of[8], of[9], of[10], of[11]));
    __stcs((float4*)&po[3 * w],     make_float4(-of[0], -of[1], -of[2], -of[3]));
    __stcs((float4*)&po[3 * w + 4], make_float4(-of[4], -of[5], -of[6], -of[7]));
    __stcs((float4*)&po[3 * w + 8], make_float4(-of[8], -of[9], -of[10], -of[11]));

    // dist_sym [E2]
    const float4 d4 = make_float4(d[0], d[1], d[2], d[3]);
    __stcs((float4*)&out[BASE_DIST + f], d4);
    __stcs((float4*)&out[BASE_DIST + w], d4);

    // vec_sym [E2, 3]
    float* pv = out + BASE_VEC;
    __stcs((float4*)&pv[3 * f],     make_float4(vx[0], vy[0], vz[0], vx[1]));
    __stcs((float4*)&pv[3 * f + 4], make_float4(vy[1], vz[1], vx[2], vy[2]));
    __stcs((float4*)&pv[3 * f + 8], make_float4(vz[2], vx[3], vy[3], vz[3]));
    __stcs((float4*)&pv[3 * w],     make_float4(-vx[0], -vy[0], -vz[0], -vx[1]));
    __stcs((float4*)&pv[3 * w + 4], make_float4(-vy[1], -vz[1], -vx[2], -vy[2]));
    __stcs((float4*)&pv[3 * w + 8], make_float4(-vz[2], -vx[3], -vy[3], -vz[3]));

    // id_swap_edge_index [E2]: analytic fwd/bwd twin permutation.
    __stcs((float4*)&out[BASE_SWAP + f],
           make_float4((float)w, (float)(w + 1), (float)(w + 2), (float)(w + 3)));
    __stcs((float4*)&out[BASE_SWAP + w],
           make_float4((float)f, (float)(f + 1), (float)(f + 2), (float)(f + 3)));

    // num_neighbors_sym (block 0 only)
    if (blk == 0 && tid < B_) {
        long long v;
        if (is64) v = ((const long long*)nn_raw)[tid];
        else      v = (long long)((const int*)nn_raw)[tid];
        out[BASE_NN + tid] = (float)(2 * v);
    }
}

extern "C" void kernel_launch(void* const* d_in, const int* in_sizes, int n_in,
                              void* d_out, int out_size) {
    const float* pos  = (const float*)d_in[0];   // [N,3] f32
    const float* cell = (const float*)d_in[1];   // [B,3,3] f32
    const void*  ei   = d_in[2];                 // [2,E] int64 or int32
    const int*   off  = (const int*)d_in[3];     // [E,3] int32
    const void*  nn   = d_in[4];                 // [B] int64 or int32
    float* out = (float*)d_out;

    graph_edges_kernel<<<GRID_, THREADS_>>>(pos, cell, ei, off, nn, out);
}

// round 12
// speedup vs baseline: 1.0036x; 1.0036x over previous
#include <cuda_runtime.h>
#include <cuda_bf16.h>

// Problem constants (fixed by the reference setup)
#define B_    64
#define NA_   2048
#define NTOT_ (B_ * NA_)        // 131072 atoms
#define EG_   40960             // directed edges per graph
#define E_    (B_ * EG_)        // 2,621,440 input edges
#define E2_   (2 * E_)          // 5,242,880 symmetrized edges

#define THREADS_  256
#define EPT_      4                     // edges per thread
#define EPB_      (THREADS_ * EPT_)     // 1024 edges/block; EG_ % EPB_ == 0 (40 blocks/graph)
#define GRID_     (E_ / EPB_)           // 2560

// Output layout: tuple members flattened row-major and concatenated, cast to f32
#define BASE_EI   0
#define BASE_OFF  (2 * E2_)                 // 10,485,760
#define BASE_DIST (BASE_OFF + 3 * E2_)      // 26,214,400
#define BASE_VEC  (BASE_DIST + E2_)         // 31,457,280
#define BASE_NN   (BASE_VEC + 3 * E2_)      // 47,185,920
#define BASE_SWAP (BASE_NN + B_)            // 47,185,984

__global__ __launch_bounds__(THREADS_, 6)   // regs <= 42; 6 blocks/SM (75% occ), smem 6x33KB fits
void graph_edges_kernel(const float* __restrict__ pos,
                        const float* __restrict__ cell,
                        const void*  __restrict__ ei_raw,
                        const int*   __restrict__ off,
                        const void*  __restrict__ nn_raw,
                        float*       __restrict__ out)
{
    __shared__ float4 s_pos[NA_];          // 32 KB: this graph's padded positions
    __shared__ int    s_is64;

    const int tid = threadIdx.x;
    const int blk = blockIdx.x;
    const int b     = blk / (EG_ / EPB_);  // graph id
    const int chunk = blk % (EG_ / EPB_);
    const int e0    = b * EG_ + chunk * EPB_;

    // Per-block dtype detection: true int64 atom indices are < 2^31; int32
    // data reinterpreted as u64 packs a (nonzero w.o.p.) src index in the
    // high half within the first 8 words.
    if (tid == 0) {
        const unsigned long long* eu = (const unsigned long long*)ei_raw;
        int is64 = 1;
        #pragma unroll
        for (int k = 0; k < 8; ++k)
            if (eu[k] >= (1ULL << 31)) { is64 = 0; break; }
        s_is64 = is64;
    }

    // Cooperative coalesced load of this graph's positions, padded to float4.
    {
        const float* pb = pos + (size_t)b * NA_ * 3;
        float* sp = (float*)s_pos;
        #pragma unroll
        for (int i = tid; i < NA_ * 3; i += THREADS_) {
            const int atom = i / 3;
            const int comp = i - atom * 3;
            sp[atom * 4 + comp] = pb[i];
        }
    }
    __syncthreads();
    const int is64 = s_is64;

    const int abase = b * NA_;
    const int e = e0 + 4 * tid;            // this thread handles edges e..e+3 (e % 4 == 0)

    // symmetrized slots: fwd f = e + b*EG (mult of 4), bwd w = f + EG (mult of 4)
    const int f = e + b * EG_;
    const int w = f + EG_;

    // ---- id_swap (no inputs needed) ----
    __stcs((float4*)&out[BASE_SWAP + f],
           make_float4((float)w, (float)(w + 1), (float)(w + 2), (float)(w + 3)));
    __stcs((float4*)&out[BASE_SWAP + w],
           make_float4((float)f, (float)(f + 1), (float)(f + 2), (float)(f + 3)));

    // ---- indices: load, store ei_sym, keep only iv/jv ints for gathers ----
    int iv[4], jv[4];
    if (is64) {
        const long long* ei = (const long long*)ei_raw;
        const longlong2 iA = __ldcs((const longlong2*)(ei + e));
        const longlong2 iB = __ldcs((const longlong2*)(ei + e + 2));
        const longlong2 jA = __ldcs((const longlong2*)(ei + E_ + e));
        const longlong2 jB = __ldcs((const longlong2*)(ei + E_ + e + 2));
        iv[0] = (int)iA.x; iv[1] = (int)iA.y; iv[2] = (int)iB.x; iv[3] = (int)iB.y;
        jv[0] = (int)jA.x; jv[1] = (int)jA.y; jv[2] = (int)jB.x; jv[3] = (int)jB.y;
    } else {
        const int* ei = (const int*)ei_raw;
        const int4 iA = __ldcs((const int4*)(ei + e));
        const int4 jA = __ldcs((const int4*)(ei + E_ + e));
        iv[0] = iA.x; iv[1] = iA.y; iv[2] = iA.z; iv[3] = iA.w;
        jv[0] = jA.x; jv[1] = jA.y; jv[2] = jA.z; jv[3] = jA.w;
    }
    {
        const float4 fiv = make_float4((float)iv[0], (float)iv[1], (float)iv[2], (float)iv[3]);
        const float4 fjv = make_float4((float)jv[0], (float)jv[1], (float)jv[2], (float)jv[3]);
        __stcs((float4*)&out[BASE_EI + f],       fiv);
        __stcs((float4*)&out[BASE_EI + E2_ + f], fjv);
        __stcs((float4*)&out[BASE_EI + w],       fjv);
        __stcs((float4*)&out[BASE_EI + E2_ + w], fiv);
    }

    // ---- cell offsets: load, store off_sym immediately ----
    float of[12];
    {
        const int4 q0 = __ldcs((const int4*)(off + 3 * e));
        const int4 q1 = __ldcs((const int4*)(off + 3 * e + 4));
        const int4 q2 = __ldcs((const int4*)(off + 3 * e + 8));
        of[0] = (float)q0.x; of[1]  = (float)q0.y; of[2]  = (float)q0.z; of[3]  = (float)q0.w;
        of[4] = (float)q1.x; of[5]  = (float)q1.y; of[6]  = (float)q1.z; of[7]  = (float)q1.w;
        of[8] = (float)q2.x; of[9]  = (float)q2.y; of[10] = (float)q2.z; of[11] = (float)q2.w;
        float* po = out + BASE_OFF;
        __stcs((float4*)&po[3 * f],     make_float4(of[0], of[1], of[2], of[3]));
        __stcs((float4*)&po[3 * f + 4], make_float4(of[4], of[5], of[6], of[7]));
        __stcs((float4*)&po[3 * f + 8], make_float4(of[8], of[9], of[10], of[11]));
        __stcs((float4*)&po[3 * w],     make_float4(-of[0], -of[1], -of[2], -of[3]));
        __stcs((float4*)&po[3 * w + 4], make_float4(-of[4], -of[5], -of[6], -of[7]));
        __stcs((float4*)&po[3 * w + 8], make_float4(-of[8], -of[9], -of[10], -of[11]));
    }

    // cell[b] broadcast (L1-resident)
    const float* cb = cell + 9 * b;
    const float c00 = cb[0], c01 = cb[1], c02 = cb[2];
    const float c10 = cb[3], c11 = cb[4], c12 = cb[5];
    const float c20 = cb[6], c21 = cb[7], c22 = cb[8];

    // ---- per-edge compute ----
    float d[4], vx[4], vy[4], vz[4];
    #pragma unroll
    for (int k = 0; k < 4; ++k) {
        const float g0 = of[3 * k], g1 = of[3 * k + 1], g2 = of[3 * k + 2];
        const float4 pi = s_pos[iv[k] - abase];
        const float4 pj = s_pos[jv[k] - abase];
        const float dx = pi.x - pj.x + (g0 * c00 + g1 * c10 + g2 * c20);
        const float dy = pi.y - pj.y + (g0 * c01 + g1 * c11 + g2 * c21);
        const float dz = pi.z - pj.z + (g0 * c02 + g1 * c12 + g2 * c22);
        d[k] = sqrtf(dx * dx + dy * dy + dz * dz);
        const float n = -1.0f / d[k];
        vx[k] = dx * n; vy[k] = dy * n; vz[k] = dz * n;
    }

    // dist_sym [E2]
    const float4 d4 = make_float4(d[0], d[1], d[2], d[3]);
    __stcs((float4*)&out[BASE_DIST + f], d4);
    __stcs((float4*)&out[BASE_DIST + w], d4);

    // vec_sym [E2, 3]
    float* pv = out + BASE_VEC;
    __stcs((float4*)&pv[3 * f],     make_float4(vx[0], vy[0], vz[0], vx[1]));
    __stcs((float4*)&pv[3 * f + 4], make_float4(vy[1], vz[1], vx[2], vy[2]));
    __stcs((float4*)&pv[3 * f + 8], make_float4(vz[2], vx[3], vy[3], vz[3]));
    __stcs((float4*)&pv[3 * w],     make_float4(-vx[0], -vy[0], -vz[0], -vx[1]));
    __stcs((float4*)&pv[3 * w + 4], make_float4(-vy[1], -vz[1], -vx[2], -vy[2]));
    __stcs((float4*)&pv[3 * w + 8], make_float4(-vz[2], -vx[3], -vy[3], -vz[3]));

    // num_neighbors_sym (block 0 only)
    if (blk == 0 && tid < B_) {
        long long v;
        if (is64) v = ((const long long*)nn_raw)[tid];
        else      v = (long long)((const int*)nn_raw)[tid];
        out[BASE_NN + tid] = (float)(2 * v);
    }
}

extern "C" void kernel_launch(void* const* d_in, const int* in_sizes, int n_in,
                              void* d_out, int out_size) {
    const float* pos  = (const float*)d_in[0];   // [N,3] f32
    const float* cell = (const float*)d_in[1];   // [B,3,3] f32
    const void*  ei   = d_in[2];                 // [2,E] int64 or int32
    const int*   off  = (const int*)d_in[3];     // [E,3] int32
    const void*  nn   = d_in[4];                 // [B] int64 or int32
    float* out = (float*)d_out;

    graph_edges_kernel<<<GRID_, THREADS_>>>(pos, cell, ei, off, nn, out);
}